// round 8
// baseline (speedup 1.0000x reference)
#include <cuda_runtime.h>
#include <stdint.h>

// CNOT permutation on a batched state vector, flattened:
//   out[g] = in[g ^ (((g >> c2) & 1) << t2)]
// where c2 = nq - control - 1, t2 = nq - target - 1, and the batch dimension
// flattens into high bits (dim = 2^nq, both bit positions < nq).
//
// Vectorized float4 path valid whenever c2 >= 2 && t2 >= 2 (bit positions
// survive the /4 index transform). Pure streaming: 1 LDG.128 + 1 STG.128
// per thread, fully coalesced on both sides (XOR of a high bit preserves
// intra-warp contiguity).

__global__ __launch_bounds__(256)
void cnot_vec4_kernel(const float4* __restrict__ in4,
                      float4* __restrict__ out4,
                      const int* __restrict__ p_control,
                      const int* __restrict__ p_target,
                      const int* __restrict__ p_nq,
                      unsigned int total4)
{
    const int nq = *p_nq;
    const int c2 = nq - *p_control - 1;
    const int t2 = nq - *p_target - 1;

    unsigned int i = blockIdx.x * blockDim.x + threadIdx.x;
    if (i >= total4) return;

    if (c2 >= 2 && t2 >= 2) {
        // float4-index space: element bit k -> float4 bit (k-2)
        const unsigned int c2v = (unsigned int)(c2 - 2);
        const unsigned int t2v = (unsigned int)(t2 - 2);
        unsigned int src = i ^ (((i >> c2v) & 1u) << t2v);
        out4[i] = in4[src];
    } else {
        // Generic scalar fallback (target or control bit inside the float4).
        const float* __restrict__ in = (const float*)in4;
        float* __restrict__ out = (float*)out4;
        unsigned int base = i << 2;
        #pragma unroll
        for (int k = 0; k < 4; k++) {
            unsigned int e = base + (unsigned int)k;
            unsigned int src = e ^ (((e >> c2) & 1u) << t2);
            out[e] = in[src];
        }
    }
}

// Scalar tail for out_size not divisible by 4 (not hit for this shape).
__global__ void cnot_tail_kernel(const float* __restrict__ in,
                                 float* __restrict__ out,
                                 const int* __restrict__ p_control,
                                 const int* __restrict__ p_target,
                                 const int* __restrict__ p_nq,
                                 unsigned int start,
                                 unsigned int total)
{
    const int nq = *p_nq;
    const int c2 = nq - *p_control - 1;
    const int t2 = nq - *p_target - 1;
    unsigned int e = start + blockIdx.x * blockDim.x + threadIdx.x;
    if (e >= total) return;
    unsigned int src = e ^ (((e >> c2) & 1u) << t2);
    out[e] = in[src];
}

extern "C" void kernel_launch(void* const* d_in, const int* in_sizes, int n_in,
                              void* d_out, int out_size)
{
    const float* state   = (const float*)d_in[0];
    const int* p_control = (const int*)d_in[1];
    const int* p_target  = (const int*)d_in[2];
    const int* p_nq      = (const int*)d_in[3];
    float* out = (float*)d_out;

    unsigned int total  = (unsigned int)out_size;
    unsigned int total4 = total >> 2;

    if (total4 > 0) {
        unsigned int blocks = (total4 + 255u) / 256u;
        cnot_vec4_kernel<<<blocks, 256>>>((const float4*)state, (float4*)out,
                                          p_control, p_target, p_nq, total4);
    }
    unsigned int done = total4 << 2;
    if (done < total) {
        unsigned int rem = total - done;
        cnot_tail_kernel<<<(rem + 255u) / 256u, 256>>>(state, out,
                                                       p_control, p_target, p_nq,
                                                       done, total);
    }
}

// round 17
// speedup vs baseline: 1.0327x; 1.0327x over previous
#include <cuda_runtime.h>
#include <stdint.h>

// CNOT permutation on a batched state vector, flattened:
//   out[g] = in[g ^ (((g >> c2) & 1) << t2)]
// c2 = nq - control - 1, t2 = nq - target - 1; batch folds into high bits.
//
// Vector path (c2>=2 && t2>=2): float4-index space, XOR of high bits only ->
// both LDG.128 and STG.128 fully coalesced. 2 float4s per thread (MLP=2),
// streaming cache hints (no reuse on either stream).

#define VEC_PER_THREAD 2u

__global__ __launch_bounds__(256)
void cnot_vec4x2_kernel(const float4* __restrict__ in4,
                        float4* __restrict__ out4,
                        const int* __restrict__ p_control,
                        const int* __restrict__ p_target,
                        const int* __restrict__ p_nq,
                        unsigned int total4)
{
    const int nq = *p_nq;
    const int c2 = nq - *p_control - 1;
    const int t2 = nq - *p_target - 1;

    const unsigned int base = blockIdx.x * (256u * VEC_PER_THREAD) + threadIdx.x;

    if (c2 >= 2 && t2 >= 2) {
        const unsigned int c2v = (unsigned int)(c2 - 2);
        const unsigned int t2v = (unsigned int)(t2 - 2);
        #pragma unroll
        for (unsigned int k = 0; k < VEC_PER_THREAD; k++) {
            unsigned int i = base + k * 256u;
            if (i < total4) {
                unsigned int src = i ^ (((i >> c2v) & 1u) << t2v);
                float4 v = __ldcs(&in4[src]);
                __stcs(&out4[i], v);
            }
        }
    } else {
        // Generic scalar fallback (control/target bit inside the float4).
        const float* __restrict__ in = (const float*)in4;
        float* __restrict__ out = (float*)out4;
        #pragma unroll
        for (unsigned int k = 0; k < VEC_PER_THREAD; k++) {
            unsigned int i = base + k * 256u;
            if (i < total4) {
                unsigned int e0 = i << 2;
                #pragma unroll
                for (int j = 0; j < 4; j++) {
                    unsigned int e = e0 + (unsigned int)j;
                    unsigned int src = e ^ (((e >> c2) & 1u) << t2);
                    out[e] = in[src];
                }
            }
        }
    }
}

// Scalar tail for out_size not divisible by 4 (not hit for this shape).
__global__ void cnot_tail_kernel(const float* __restrict__ in,
                                 float* __restrict__ out,
                                 const int* __restrict__ p_control,
                                 const int* __restrict__ p_target,
                                 const int* __restrict__ p_nq,
                                 unsigned int start,
                                 unsigned int total)
{
    const int nq = *p_nq;
    const int c2 = nq - *p_control - 1;
    const int t2 = nq - *p_target - 1;
    unsigned int e = start + blockIdx.x * blockDim.x + threadIdx.x;
    if (e >= total) return;
    unsigned int src = e ^ (((e >> c2) & 1u) << t2);
    out[e] = in[src];
}

extern "C" void kernel_launch(void* const* d_in, const int* in_sizes, int n_in,
                              void* d_out, int out_size)
{
    const float* state   = (const float*)d_in[0];
    const int* p_control = (const int*)d_in[1];
    const int* p_target  = (const int*)d_in[2];
    const int* p_nq      = (const int*)d_in[3];
    float* out = (float*)d_out;

    unsigned int total  = (unsigned int)out_size;
    unsigned int total4 = total >> 2;

    if (total4 > 0) {
        unsigned int per_block = 256u * VEC_PER_THREAD;
        unsigned int blocks = (total4 + per_block - 1u) / per_block;
        cnot_vec4x2_kernel<<<blocks, 256>>>((const float4*)state, (float4*)out,
                                            p_control, p_target, p_nq, total4);
    }
    unsigned int done = total4 << 2;
    if (done < total) {
        unsigned int rem = total - done;
        cnot_tail_kernel<<<(rem + 255u) / 256u, 256>>>(state, out,
                                                       p_control, p_target, p_nq,
                                                       done, total);
    }
}